// round 4
// baseline (speedup 1.0000x reference)
#include <cuda_runtime.h>
#include <cuda_bf16.h>
#include <cstdint>

// GCN with folded normalization + PADDED CSR:
//   xw'[v] = (x@W)[v] * dinvs[v]
//   out[d] = dinvs[d] * ( sum_{edges s->d} xw'[s] + xw'[d] ) + b
// Every CSR row is padded to a multiple of 32 with ZROW (an all-zero feature
// row) so the gather loop has NO serial tail. Layers fuse bias+LN+ReLU+next
// GEMM. gemm1 uses packed fma.rn.f32x2.

#define N_MAX 100000
#define E_MAX 3200000
#define E_PAD_MAX (E_MAX + 32 * N_MAX)   // worst-case padded CSR length
#define IN_CH 128
#define HID   32
#define LN_EPS 1e-5f
#define SCAN_B 1024
#define ZROW  N_MAX                      // index of the zero feature row

// ---------------- device scratch ----------------
__device__ int   g_cnt[N_MAX];
__device__ int   g_rowstart[N_MAX + 1];  // padded prefix
__device__ int   g_cursor[N_MAX];
__device__ float g_dinvs[N_MAX];
__device__ int   g_src[E_PAD_MAX];
__device__ int   g_bsum[128];            // per-scan-block padded sums
__device__ float g_xw[(N_MAX + 1) * HID];
__device__ float g_hw2[(N_MAX + 1) * HID];
__device__ float g_hw3[(N_MAX + 1) * 2];

// ---------------- 0: init (zero counts, zero rows, prefill CSR with ZROW) ---
__global__ void init_kernel(int n) {
    int i = blockIdx.x * blockDim.x + threadIdx.x;
    // prefill g_src with ZROW (int4 stores)
    int np4 = E_PAD_MAX / 4;
    if (i < np4) ((int4*)g_src)[i] = make_int4(ZROW, ZROW, ZROW, ZROW);
    if (i < n) g_cnt[i] = 0;
    if (i < HID) {
        g_xw[ZROW * HID + i] = 0.f;
        g_hw2[ZROW * HID + i] = 0.f;
    }
    if (i < 2) g_hw3[ZROW * 2 + i] = 0.f;
}

// ---------------- 1: degree counts over dst (int4 reads) ----------------
__global__ void count_kernel(const int* __restrict__ ei, int e) {
    int i = blockIdx.x * blockDim.x + threadIdx.x;
    int n4 = e >> 2;
    if (i < n4) {
        int4 d4 = ((const int4*)(ei + e))[i];
        atomicAdd(&g_cnt[d4.x], 1);
        atomicAdd(&g_cnt[d4.y], 1);
        atomicAdd(&g_cnt[d4.z], 1);
        atomicAdd(&g_cnt[d4.w], 1);
    }
    if (i == 0) {
        for (int j = n4 << 2; j < e; j++) atomicAdd(&g_cnt[ei[e + j]], 1);
    }
}

// ---------------- 2a: per-block sums of PADDED counts ----------------
__global__ void blocksum_kernel(int n) {
    __shared__ int ws[32];
    int tid = threadIdx.x, lane = tid & 31, wid = tid >> 5;
    int i = blockIdx.x * SCAN_B + tid;
    int v = (i < n) ? g_cnt[i] : 0;
    int pc = (v + 31) & ~31;
    int s = pc;
    #pragma unroll
    for (int d = 16; d; d >>= 1) s += __shfl_xor_sync(0xFFFFFFFFu, s, d);
    if (lane == 0) ws[wid] = s;
    __syncthreads();
    if (wid == 0) {
        int t = ws[lane];
        #pragma unroll
        for (int d = 16; d; d >>= 1) t += __shfl_xor_sync(0xFFFFFFFFu, t, d);
        if (lane == 0) g_bsum[blockIdx.x] = t;
    }
}

// ---------------- 2b: local scan of padded counts + degree terms ----------
__global__ void scan2_kernel(int n, int nb) {
    __shared__ int wsum[32];
    __shared__ int boff_s;
    int tid = threadIdx.x, lane = tid & 31, wid = tid >> 5;

    // compute this block's offset = sum of g_bsum[0..bid)
    if (tid == 0) boff_s = 0;
    __syncthreads();
    if (tid < 128) {
        int bv = (tid < blockIdx.x) ? g_bsum[tid] : 0;
        #pragma unroll
        for (int d = 16; d; d >>= 1) bv += __shfl_xor_sync(0xFFFFFFFFu, bv, d);
        if (lane == 0 && bv) atomicAdd(&boff_s, bv);
    }

    int i = blockIdx.x * SCAN_B + tid;
    int v = (i < n) ? g_cnt[i] : 0;
    int pc = (v + 31) & ~31;
    int x = pc;
    #pragma unroll
    for (int d = 1; d < 32; d <<= 1) {
        int t = __shfl_up_sync(0xFFFFFFFFu, x, d);
        if (lane >= d) x += t;
    }
    if (lane == 31) wsum[wid] = x;
    __syncthreads();
    if (wid == 0) {
        int s = wsum[lane];
        #pragma unroll
        for (int d = 1; d < 32; d <<= 1) {
            int t = __shfl_up_sync(0xFFFFFFFFu, s, d);
            if (lane >= d) s += t;
        }
        wsum[lane] = s;
    }
    __syncthreads();
    if (i < n) {
        int excl = boff_s + (wid > 0 ? wsum[wid - 1] : 0) + x - pc;
        g_rowstart[i] = excl;
        g_cursor[i]   = excl;
        g_dinvs[i] = rsqrtf((float)v + 1.0f);
        if (i == n - 1) g_rowstart[n] = excl + pc;
    }
}

// ---------------- 3: fill CSR (src only) ----------------
__global__ void fill_kernel(const int* __restrict__ ei, int e) {
    int i = blockIdx.x * blockDim.x + threadIdx.x;
    if (i < e) {
        int s = ei[i];
        int d = ei[e + i];
        int p = atomicAdd(&g_cursor[d], 1);
        g_src[p] = s;
    }
}

// ---------------- 4: GEMM1  g_xw = (x @ W1) * dinvs  (fma.rn.f32x2) -------
__global__ void gemm1_kernel(const float* __restrict__ x,
                             const float* __restrict__ W1, int n) {
    __shared__ __align__(16) float Ws[128 * 32];
    __shared__ __align__(16) float xs[128 * 33];
    int tid = threadIdx.x;
    for (int i = tid; i < 128 * 32; i += 256) Ws[i] = W1[i];

    int tx = tid & 7;    // channel group tx*4..+3 (2 packed pairs)
    int ty = tid >> 3;   // node group   ty*4..+3
    int wid = tid >> 5, lane = tid & 31;
    int nodeBase = blockIdx.x * 128;

    unsigned long long acc2[4][2];
    #pragma unroll
    for (int i = 0; i < 4; i++) { acc2[i][0] = 0ull; acc2[i][1] = 0ull; }

    for (int kc = 0; kc < 4; kc++) {
        __syncthreads();
        for (int r = wid; r < 128; r += 8) {
            int gn = nodeBase + r;
            float v = 0.f;
            if (gn < n) v = x[gn * IN_CH + kc * 32 + lane];
            xs[r * 33 + lane] = v;
        }
        __syncthreads();
        #pragma unroll
        for (int k = 0; k < 32; k++) {
            const unsigned long long* wp =
                (const unsigned long long*)&Ws[(kc * 32 + k) * 32 + tx * 4];
            unsigned long long w0 = wp[0], w1 = wp[1];
            #pragma unroll
            for (int i = 0; i < 4; i++) {
                float xv = xs[(ty * 4 + i) * 33 + k];
                unsigned long long xp;
                asm("mov.b64 %0, {%1, %1};" : "=l"(xp) : "f"(xv));
                asm("fma.rn.f32x2 %0, %1, %2, %0;" : "+l"(acc2[i][0]) : "l"(xp), "l"(w0));
                asm("fma.rn.f32x2 %0, %1, %2, %0;" : "+l"(acc2[i][1]) : "l"(xp), "l"(w1));
            }
        }
    }
    #pragma unroll
    for (int i = 0; i < 4; i++) {
        int gn = nodeBase + ty * 4 + i;
        if (gn < n) {
            float ds = g_dinvs[gn];
            unsigned long long dp, r0, r1;
            asm("mov.b64 %0, {%1, %1};" : "=l"(dp) : "f"(ds));
            asm("mul.rn.f32x2 %0, %1, %2;" : "=l"(r0) : "l"(acc2[i][0]), "l"(dp));
            asm("mul.rn.f32x2 %0, %1, %2;" : "=l"(r1) : "l"(acc2[i][1]), "l"(dp));
            ulonglong2 st; st.x = r0; st.y = r1;
            *(ulonglong2*)&g_xw[gn * HID + tx * 4] = st;
        }
    }
}

// ---------------- 5/6: gather-agg + bias + LN + ReLU + next GEMM ----------
// MODE 0: in = g_xw,  out = g_hw2 via W2[32,32]
// MODE 1: in = g_hw2, out = g_hw3 via W3[32,2]
template <int MODE>
__global__ void agg_kernel(const float* __restrict__ b,
                           const float* __restrict__ g,
                           const float* __restrict__ be,
                           const float* __restrict__ Wn, int n) {
    const float* __restrict__ xw = (MODE == 0) ? g_xw : g_hw2;
    __shared__ float Wns[32 * 32];
    int tid = threadIdx.x, lane = tid & 31, wid = tid >> 5;
    int nload = (MODE == 0) ? 1024 : 64;
    for (int i = tid; i < nload; i += blockDim.x) Wns[i] = Wn[i];
    __syncthreads();

    int node = blockIdx.x * 8 + wid;
    if (node >= n) return;

    int rs = g_rowstart[node];
    int re = g_rowstart[node + 1];   // padded: (re-rs) % 32 == 0

    float acc = 0.f;
    for (int base = rs; base < re; base += 32) {
        int sidx = g_src[base + lane];
        float a0 = 0.f, a1 = 0.f, a2 = 0.f, a3 = 0.f;
        #pragma unroll
        for (int j = 0; j < 32; j += 4) {
            int s0 = __shfl_sync(0xFFFFFFFFu, sidx, j + 0);
            int s1 = __shfl_sync(0xFFFFFFFFu, sidx, j + 1);
            int s2 = __shfl_sync(0xFFFFFFFFu, sidx, j + 2);
            int s3 = __shfl_sync(0xFFFFFFFFu, sidx, j + 3);
            a0 += xw[s0 * HID + lane];
            a1 += xw[s1 * HID + lane];
            a2 += xw[s2 * HID + lane];
            a3 += xw[s3 * HID + lane];
        }
        acc += (a0 + a1) + (a2 + a3);
    }

    // self loop, scale by dinvs[dst], bias
    float ds = g_dinvs[node];
    acc = (acc + xw[node * HID + lane]) * ds + b[lane];

    // LayerNorm over the 32 lanes
    float s = acc;
    #pragma unroll
    for (int d = 16; d; d >>= 1) s += __shfl_xor_sync(0xFFFFFFFFu, s, d);
    float mu = s * (1.0f / 32.0f);
    float diff = acc - mu;
    float v2 = diff * diff;
    #pragma unroll
    for (int d = 16; d; d >>= 1) v2 += __shfl_xor_sync(0xFFFFFFFFu, v2, d);
    float var = v2 * (1.0f / 32.0f);
    float y = diff * rsqrtf(var + LN_EPS) * g[lane] + be[lane];
    float h = fmaxf(y, 0.f);

    if (MODE == 0) {
        float o0 = 0.f, o1 = 0.f;
        #pragma unroll
        for (int k = 0; k < 32; k += 2) {
            float h0 = __shfl_sync(0xFFFFFFFFu, h, k);
            float h1 = __shfl_sync(0xFFFFFFFFu, h, k + 1);
            o0 = fmaf(h0, Wns[k * 32 + lane], o0);
            o1 = fmaf(h1, Wns[(k + 1) * 32 + lane], o1);
        }
        g_hw2[node * HID + lane] = (o0 + o1) * ds;
    } else {
        float p0 = h * Wns[lane * 2 + 0];
        float p1 = h * Wns[lane * 2 + 1];
        #pragma unroll
        for (int d = 16; d; d >>= 1) {
            p0 += __shfl_xor_sync(0xFFFFFFFFu, p0, d);
            p1 += __shfl_xor_sync(0xFFFFFFFFu, p1, d);
        }
        if (lane == 0) {
            float2 r; r.x = p0 * ds; r.y = p1 * ds;
            *(float2*)&g_hw3[node * 2] = r;
        }
    }
}

// ---------------- 7: final conv (OUT=2) ----------------
__global__ void final_kernel(const float* __restrict__ b3,
                             float* __restrict__ out, int n) {
    int tid = threadIdx.x, lane = tid & 31, wid = tid >> 5;
    int node = blockIdx.x * 8 + wid;
    if (node >= n) return;
    int rs = g_rowstart[node];
    int re = g_rowstart[node + 1];
    float a0 = 0.f, a1 = 0.f;
    for (int idx = rs + lane; idx < re; idx += 32) {
        float2 v = *(const float2*)&g_hw3[g_src[idx] * 2];  // pads hit zero row
        a0 += v.x;
        a1 += v.y;
    }
    #pragma unroll
    for (int d = 16; d; d >>= 1) {
        a0 += __shfl_xor_sync(0xFFFFFFFFu, a0, d);
        a1 += __shfl_xor_sync(0xFFFFFFFFu, a1, d);
    }
    if (lane == 0) {
        float2 self = *(const float2*)&g_hw3[node * 2];
        float ds = g_dinvs[node];
        out[node * 2 + 0] = (a0 + self.x) * ds + b3[0];
        out[node * 2 + 1] = (a1 + self.y) * ds + b3[1];
    }
}

// ---------------- launch ----------------
extern "C" void kernel_launch(void* const* d_in, const int* in_sizes, int n_in,
                              void* d_out, int out_size) {
    const float* x   = (const float*)d_in[0];
    const int*   ei  = (const int*)d_in[1];
    const float* W1  = (const float*)d_in[2];
    const float* b1  = (const float*)d_in[3];
    const float* g1  = (const float*)d_in[4];
    const float* be1 = (const float*)d_in[5];
    const float* W2  = (const float*)d_in[6];
    const float* b2  = (const float*)d_in[7];
    const float* g2  = (const float*)d_in[8];
    const float* be2 = (const float*)d_in[9];
    const float* W3  = (const float*)d_in[10];
    const float* b3  = (const float*)d_in[11];
    float* out = (float*)d_out;

    int n = in_sizes[0] / IN_CH;   // 100000
    int e = in_sizes[1] / 2;       // 3200000
    int nb = (n + SCAN_B - 1) / SCAN_B;

    init_kernel<<<(E_PAD_MAX / 4 + 255) / 256, 256>>>(n);
    count_kernel<<<(e / 4 + 255) / 256, 256>>>(ei, e);
    blocksum_kernel<<<nb, SCAN_B>>>(n);
    scan2_kernel<<<nb, SCAN_B>>>(n, nb);
    fill_kernel<<<(e + 255) / 256, 256>>>(ei, e);
    gemm1_kernel<<<(n + 127) / 128, 256>>>(x, W1, n);
    agg_kernel<0><<<(n + 7) / 8, 256>>>(b1, g1, be1, W2, n);
    agg_kernel<1><<<(n + 7) / 8, 256>>>(b2, g2, be2, W3, n);
    final_kernel<<<(n + 7) / 8, 256>>>(b3, out, n);
}

// round 5
// speedup vs baseline: 1.0493x; 1.0493x over previous
#include <cuda_runtime.h>
#include <cuda_bf16.h>
#include <cstdint>

// GCN with folded normalization:
//   xw'[v] = (x@W)[v] * dinvs[v]
//   out[d] = dinvs[d] * ( sum_{edges s->d} xw'[s] + xw'[d] ) + b
// Exact-length CSR (src only). Aggregation uses a float4 gather layout:
// warp = 1 node, lane -> (edge subgroup eg = lane>>3, channel group cg = lane&7);
// per iteration: 1 shfl (4 edge indices) + 1 LDG.128 + 2 add.f32x2.
// Out-of-row lanes clamp to ZROW (zero feature row) => no serial tail,
// no physical padding. Epilogue transposes via smem, then bias+LN+ReLU+next GEMM.

#define N_MAX 100000
#define E_MAX 3200000
#define IN_CH 128
#define HID   32
#define LN_EPS 1e-5f
#define SCAN_B 1024
#define ZROW  N_MAX

// ---------------- device scratch ----------------
__device__ int   g_cnt[N_MAX];
__device__ int   g_rowstart[N_MAX + 1];
__device__ int   g_cursor[N_MAX];
__device__ float g_dinvs[N_MAX];
__device__ int   g_src[E_MAX + 32];      // slack so batch reads never fault
__device__ int   g_bsum[128];
__device__ __align__(16) float g_xw[(N_MAX + 1) * HID];
__device__ __align__(16) float g_hw2[(N_MAX + 1) * HID];
__device__ float g_hw3[(N_MAX + 1) * 2];

// ---------------- 0: init (zero counts + zero rows) ----------------
__global__ void init_kernel(int n) {
    int i = blockIdx.x * blockDim.x + threadIdx.x;
    if (i < n) g_cnt[i] = 0;
    if (i < HID) {
        g_xw[ZROW * HID + i] = 0.f;
        g_hw2[ZROW * HID + i] = 0.f;
    }
    if (i < 2) g_hw3[ZROW * 2 + i] = 0.f;
}

// ---------------- 1: degree counts over dst (int4 reads) ----------------
__global__ void count_kernel(const int* __restrict__ ei, int e) {
    int i = blockIdx.x * blockDim.x + threadIdx.x;
    int n4 = e >> 2;
    if (i < n4) {
        int4 d4 = ((const int4*)(ei + e))[i];
        atomicAdd(&g_cnt[d4.x], 1);
        atomicAdd(&g_cnt[d4.y], 1);
        atomicAdd(&g_cnt[d4.z], 1);
        atomicAdd(&g_cnt[d4.w], 1);
    }
    if (i == 0) {
        for (int j = n4 << 2; j < e; j++) atomicAdd(&g_cnt[ei[e + j]], 1);
    }
}

// ---------------- 2a: per-block sums of counts ----------------
__global__ void blocksum_kernel(int n) {
    __shared__ int ws[32];
    int tid = threadIdx.x, lane = tid & 31, wid = tid >> 5;
    int i = blockIdx.x * SCAN_B + tid;
    int v = (i < n) ? g_cnt[i] : 0;
    int s = v;
    #pragma unroll
    for (int d = 16; d; d >>= 1) s += __shfl_xor_sync(0xFFFFFFFFu, s, d);
    if (lane == 0) ws[wid] = s;
    __syncthreads();
    if (wid == 0) {
        int t = ws[lane];
        #pragma unroll
        for (int d = 16; d; d >>= 1) t += __shfl_xor_sync(0xFFFFFFFFu, t, d);
        if (lane == 0) g_bsum[blockIdx.x] = t;
    }
}

// ---------------- 2b: local scan + degree terms (block offset inline) ------
__global__ void scan2_kernel(int n, int nb) {
    __shared__ int wsum[32];
    __shared__ int boff_s;
    int tid = threadIdx.x, lane = tid & 31, wid = tid >> 5;

    if (tid == 0) boff_s = 0;
    __syncthreads();
    if (tid < 128) {
        int bv = (tid < blockIdx.x) ? g_bsum[tid] : 0;
        #pragma unroll
        for (int d = 16; d; d >>= 1) bv += __shfl_xor_sync(0xFFFFFFFFu, bv, d);
        if (lane == 0 && bv) atomicAdd(&boff_s, bv);
    }

    int i = blockIdx.x * SCAN_B + tid;
    int v = (i < n) ? g_cnt[i] : 0;
    int x = v;
    #pragma unroll
    for (int d = 1; d < 32; d <<= 1) {
        int t = __shfl_up_sync(0xFFFFFFFFu, x, d);
        if (lane >= d) x += t;
    }
    if (lane == 31) wsum[wid] = x;
    __syncthreads();
    if (wid == 0) {
        int s = wsum[lane];
        #pragma unroll
        for (int d = 1; d < 32; d <<= 1) {
            int t = __shfl_up_sync(0xFFFFFFFFu, s, d);
            if (lane >= d) s += t;
        }
        wsum[lane] = s;
    }
    __syncthreads();
    if (i < n) {
        int excl = boff_s + (wid > 0 ? wsum[wid - 1] : 0) + x - v;
        g_rowstart[i] = excl;
        g_cursor[i]   = excl;
        g_dinvs[i] = rsqrtf((float)v + 1.0f);
        if (i == n - 1) g_rowstart[n] = excl + v;
    }
}

// ---------------- 3: fill CSR (src only) ----------------
__global__ void fill_kernel(const int* __restrict__ ei, int e) {
    int i = blockIdx.x * blockDim.x + threadIdx.x;
    if (i < e) {
        int s = ei[i];
        int d = ei[e + i];
        int p = atomicAdd(&g_cursor[d], 1);
        g_src[p] = s;
    }
}

// ---------------- 4: GEMM1  g_xw = (x @ W1) * dinvs  (fma.rn.f32x2) -------
__global__ void gemm1_kernel(const float* __restrict__ x,
                             const float* __restrict__ W1, int n) {
    __shared__ __align__(16) float Ws[128 * 32];
    __shared__ __align__(16) float xs[128 * 33];
    int tid = threadIdx.x;
    for (int i = tid; i < 128 * 32; i += 256) Ws[i] = W1[i];

    int tx = tid & 7;
    int ty = tid >> 3;
    int wid = tid >> 5, lane = tid & 31;
    int nodeBase = blockIdx.x * 128;

    unsigned long long acc2[4][2];
    #pragma unroll
    for (int i = 0; i < 4; i++) { acc2[i][0] = 0ull; acc2[i][1] = 0ull; }

    for (int kc = 0; kc < 4; kc++) {
        __syncthreads();
        for (int r = wid; r < 128; r += 8) {
            int gn = nodeBase + r;
            float v = 0.f;
            if (gn < n) v = x[gn * IN_CH + kc * 32 + lane];
            xs[r * 33 + lane] = v;
        }
        __syncthreads();
        #pragma unroll
        for (int k = 0; k < 32; k++) {
            const unsigned long long* wp =
                (const unsigned long long*)&Ws[(kc * 32 + k) * 32 + tx * 4];
            unsigned long long w0 = wp[0], w1 = wp[1];
            #pragma unroll
            for (int i = 0; i < 4; i++) {
                float xv = xs[(ty * 4 + i) * 33 + k];
                unsigned long long xp;
                asm("mov.b64 %0, {%1, %1};" : "=l"(xp) : "f"(xv));
                asm("fma.rn.f32x2 %0, %1, %2, %0;" : "+l"(acc2[i][0]) : "l"(xp), "l"(w0));
                asm("fma.rn.f32x2 %0, %1, %2, %0;" : "+l"(acc2[i][1]) : "l"(xp), "l"(w1));
            }
        }
    }
    #pragma unroll
    for (int i = 0; i < 4; i++) {
        int gn = nodeBase + ty * 4 + i;
        if (gn < n) {
            float ds = g_dinvs[gn];
            unsigned long long dp, r0, r1;
            asm("mov.b64 %0, {%1, %1};" : "=l"(dp) : "f"(ds));
            asm("mul.rn.f32x2 %0, %1, %2;" : "=l"(r0) : "l"(acc2[i][0]), "l"(dp));
            asm("mul.rn.f32x2 %0, %1, %2;" : "=l"(r1) : "l"(acc2[i][1]), "l"(dp));
            ulonglong2 st; st.x = r0; st.y = r1;
            *(ulonglong2*)&g_xw[gn * HID + tx * 4] = st;
        }
    }
}

// ---------------- 5/6: float4 gather-agg + bias + LN + ReLU + next GEMM ---
// MODE 0: in = g_xw,  out = g_hw2 via W2[32,32]
// MODE 1: in = g_hw2, out = g_hw3 via W3[32,2]
template <int MODE>
__global__ void agg_kernel(const float* __restrict__ b,
                           const float* __restrict__ g,
                           const float* __restrict__ be,
                           const float* __restrict__ Wn, int n) {
    const float* __restrict__ xw = (MODE == 0) ? g_xw : g_hw2;
    __shared__ float Wns[32 * 32];
    __shared__ float tr[8 * 32];
    int tid = threadIdx.x, lane = tid & 31, wid = tid >> 5;
    int nload = (MODE == 0) ? 1024 : 64;
    for (int i = tid; i < nload; i += blockDim.x) Wns[i] = Wn[i];
    __syncthreads();

    int node = blockIdx.x * 8 + wid;
    if (node >= n) return;

    int rs = g_rowstart[node];
    int re = g_rowstart[node + 1];
    int cg = lane & 7;    // channel group: channels cg*4..cg*4+3
    int eg = lane >> 3;   // edge subgroup 0..3

    unsigned long long a0 = 0ull, a1 = 0ull;   // float4 accumulator (2x f32x2)
    for (int base = rs; base < re; base += 32) {
        int idx = base + lane;
        int sidx = (idx < re) ? g_src[idx] : ZROW;
        #pragma unroll
        for (int it = 0; it < 8; it++) {
            int s = __shfl_sync(0xFFFFFFFFu, sidx, it * 4 + eg);
            ulonglong2 v = *(const ulonglong2*)&xw[s * HID + cg * 4];
            asm("add.rn.f32x2 %0, %0, %1;" : "+l"(a0) : "l"(v.x));
            asm("add.rn.f32x2 %0, %0, %1;" : "+l"(a1) : "l"(v.y));
        }
    }

    // unpack and reduce across edge subgroups (lane bits 3,4)
    float f0, f1, f2, f3;
    asm("mov.b64 {%0, %1}, %2;" : "=f"(f0), "=f"(f1) : "l"(a0));
    asm("mov.b64 {%0, %1}, %2;" : "=f"(f2), "=f"(f3) : "l"(a1));
    #pragma unroll
    for (int m = 8; m <= 16; m <<= 1) {
        f0 += __shfl_xor_sync(0xFFFFFFFFu, f0, m);
        f1 += __shfl_xor_sync(0xFFFFFFFFu, f1, m);
        f2 += __shfl_xor_sync(0xFFFFFFFFu, f2, m);
        f3 += __shfl_xor_sync(0xFFFFFFFFu, f3, m);
    }
    // transpose to lane = channel via smem
    if (eg == 0) {
        float4 st; st.x = f0; st.y = f1; st.z = f2; st.w = f3;
        *(float4*)&tr[wid * 32 + cg * 4] = st;
    }
    __syncwarp();
    float acc = tr[wid * 32 + lane];

    // self loop, scale by dinvs[dst], bias
    float ds = g_dinvs[node];
    acc = (acc + xw[node * HID + lane]) * ds + b[lane];

    // LayerNorm over the 32 lanes
    float s = acc;
    #pragma unroll
    for (int d = 16; d; d >>= 1) s += __shfl_xor_sync(0xFFFFFFFFu, s, d);
    float mu = s * (1.0f / 32.0f);
    float diff = acc - mu;
    float v2 = diff * diff;
    #pragma unroll
    for (int d = 16; d; d >>= 1) v2 += __shfl_xor_sync(0xFFFFFFFFu, v2, d);
    float var = v2 * (1.0f / 32.0f);
    float y = diff * rsqrtf(var + LN_EPS) * g[lane] + be[lane];
    float h = fmaxf(y, 0.f);

    if (MODE == 0) {
        float o0 = 0.f, o1 = 0.f;
        #pragma unroll
        for (int k = 0; k < 32; k += 2) {
            float h0 = __shfl_sync(0xFFFFFFFFu, h, k);
            float h1 = __shfl_sync(0xFFFFFFFFu, h, k + 1);
            o0 = fmaf(h0, Wns[k * 32 + lane], o0);
            o1 = fmaf(h1, Wns[(k + 1) * 32 + lane], o1);
        }
        g_hw2[node * HID + lane] = (o0 + o1) * ds;
    } else {
        float p0 = h * Wns[lane * 2 + 0];
        float p1 = h * Wns[lane * 2 + 1];
        #pragma unroll
        for (int d = 16; d; d >>= 1) {
            p0 += __shfl_xor_sync(0xFFFFFFFFu, p0, d);
            p1 += __shfl_xor_sync(0xFFFFFFFFu, p1, d);
        }
        if (lane == 0) {
            float2 r; r.x = p0 * ds; r.y = p1 * ds;
            *(float2*)&g_hw3[node * 2] = r;
        }
    }
}

// ---------------- 7: final conv (OUT=2) ----------------
__global__ void final_kernel(const float* __restrict__ b3,
                             float* __restrict__ out, int n) {
    int tid = threadIdx.x, lane = tid & 31, wid = tid >> 5;
    int node = blockIdx.x * 8 + wid;
    if (node >= n) return;
    int rs = g_rowstart[node];
    int re = g_rowstart[node + 1];
    float a0 = 0.f, a1 = 0.f;
    for (int idx = rs + lane; idx < re; idx += 32) {
        float2 v = *(const float2*)&g_hw3[g_src[idx] * 2];
        a0 += v.x;
        a1 += v.y;
    }
    #pragma unroll
    for (int d = 16; d; d >>= 1) {
        a0 += __shfl_xor_sync(0xFFFFFFFFu, a0, d);
        a1 += __shfl_xor_sync(0xFFFFFFFFu, a1, d);
    }
    if (lane == 0) {
        float2 self = *(const float2*)&g_hw3[node * 2];
        float ds = g_dinvs[node];
        out[node * 2 + 0] = (a0 + self.x) * ds + b3[0];
        out[node * 2 + 1] = (a1 + self.y) * ds + b3[1];
    }
}

// ---------------- launch ----------------
extern "C" void kernel_launch(void* const* d_in, const int* in_sizes, int n_in,
                              void* d_out, int out_size) {
    const float* x   = (const float*)d_in[0];
    const int*   ei  = (const int*)d_in[1];
    const float* W1  = (const float*)d_in[2];
    const float* b1  = (const float*)d_in[3];
    const float* g1  = (const float*)d_in[4];
    const float* be1 = (const float*)d_in[5];
    const float* W2  = (const float*)d_in[6];
    const float* b2  = (const float*)d_in[7];
    const float* g2  = (const float*)d_in[8];
    const float* be2 = (const float*)d_in[9];
    const float* W3  = (const float*)d_in[10];
    const float* b3  = (const float*)d_in[11];
    float* out = (float*)d_out;

    int n = in_sizes[0] / IN_CH;   // 100000
    int e = in_sizes[1] / 2;       // 3200000
    int nb = (n + SCAN_B - 1) / SCAN_B;

    init_kernel<<<(n + 255) / 256, 256>>>(n);
    count_kernel<<<(e / 4 + 255) / 256, 256>>>(ei, e);
    blocksum_kernel<<<nb, SCAN_B>>>(n);
    scan2_kernel<<<nb, SCAN_B>>>(n, nb);
    fill_kernel<<<(e + 255) / 256, 256>>>(ei, e);
    gemm1_kernel<<<(n + 127) / 128, 256>>>(x, W1, n);
    agg_kernel<0><<<(n + 7) / 8, 256>>>(b1, g1, be1, W2, n);
    agg_kernel<1><<<(n + 7) / 8, 256>>>(b2, g2, be2, W3, n);
    final_kernel<<<(n + 7) / 8, 256>>>(b3, out, n);
}

// round 6
// speedup vs baseline: 1.1298x; 1.0766x over previous
#include <cuda_runtime.h>
#include <cuda_fp16.h>
#include <cuda_bf16.h>
#include <cstdint>

// GCN with folded normalization, fp16 feature tables, fp32 accumulation:
//   xw'[v] = (x@W)[v] * dinvs[v]            (stored as __half)
//   out[d] = dinvs[d] * ( sum_edges xw'[s] + xw'[d] ) + b
// Exact-length CSR (src only). Aggregation: warp = node, lane -> (edge
// subgroup eg = lane>>3, channel group cg = lane&7); per iter 1 shfl + 1
// LDG.64 (4 halves) + fp32 adds. Out-of-row lanes clamp to ZROW (zero row).

#define N_MAX 100000
#define E_MAX 3200000
#define IN_CH 128
#define HID   32
#define LN_EPS 1e-5f
#define SCAN_B 1024
#define ZROW  N_MAX

// ---------------- device scratch ----------------
__device__ int    g_cnt[N_MAX];
__device__ int    g_rowstart[N_MAX + 1];
__device__ int    g_cursor[N_MAX];
__device__ float  g_dinvs[N_MAX];
__device__ int    g_src[E_MAX + 32];
__device__ int    g_bsum[128];
__device__ __align__(16) __half g_xw[(N_MAX + 1) * HID];
__device__ __align__(16) __half g_hw2[(N_MAX + 1) * HID];
__device__ float  g_hw3[(N_MAX + 1) * 2];

// ---------------- 0: init (zero counts + zero rows) ----------------
__global__ void init_kernel(int n) {
    int i = blockIdx.x * blockDim.x + threadIdx.x;
    if (i < n) g_cnt[i] = 0;
    if (i < HID) {
        g_xw[ZROW * HID + i] = __float2half(0.f);
        g_hw2[ZROW * HID + i] = __float2half(0.f);
    }
    if (i < 2) g_hw3[ZROW * 2 + i] = 0.f;
}

// ---------------- 1: degree counts over dst (int4 reads) ----------------
__global__ void count_kernel(const int* __restrict__ ei, int e) {
    int i = blockIdx.x * blockDim.x + threadIdx.x;
    int n4 = e >> 2;
    if (i < n4) {
        int4 d4 = ((const int4*)(ei + e))[i];
        atomicAdd(&g_cnt[d4.x], 1);
        atomicAdd(&g_cnt[d4.y], 1);
        atomicAdd(&g_cnt[d4.z], 1);
        atomicAdd(&g_cnt[d4.w], 1);
    }
    if (i == 0) {
        for (int j = n4 << 2; j < e; j++) atomicAdd(&g_cnt[ei[e + j]], 1);
    }
}

// ---------------- 2a: per-block sums of counts ----------------
__global__ void blocksum_kernel(int n) {
    __shared__ int ws[32];
    int tid = threadIdx.x, lane = tid & 31, wid = tid >> 5;
    int i = blockIdx.x * SCAN_B + tid;
    int v = (i < n) ? g_cnt[i] : 0;
    int s = v;
    #pragma unroll
    for (int d = 16; d; d >>= 1) s += __shfl_xor_sync(0xFFFFFFFFu, s, d);
    if (lane == 0) ws[wid] = s;
    __syncthreads();
    if (wid == 0) {
        int t = ws[lane];
        #pragma unroll
        for (int d = 16; d; d >>= 1) t += __shfl_xor_sync(0xFFFFFFFFu, t, d);
        if (lane == 0) g_bsum[blockIdx.x] = t;
    }
}

// ---------------- 2b: local scan + degree terms ----------------
__global__ void scan2_kernel(int n, int nb) {
    __shared__ int wsum[32];
    __shared__ int boff_s;
    int tid = threadIdx.x, lane = tid & 31, wid = tid >> 5;

    if (tid == 0) boff_s = 0;
    __syncthreads();
    if (tid < 128) {
        int bv = (tid < blockIdx.x) ? g_bsum[tid] : 0;
        #pragma unroll
        for (int d = 16; d; d >>= 1) bv += __shfl_xor_sync(0xFFFFFFFFu, bv, d);
        if (lane == 0 && bv) atomicAdd(&boff_s, bv);
    }

    int i = blockIdx.x * SCAN_B + tid;
    int v = (i < n) ? g_cnt[i] : 0;
    int x = v;
    #pragma unroll
    for (int d = 1; d < 32; d <<= 1) {
        int t = __shfl_up_sync(0xFFFFFFFFu, x, d);
        if (lane >= d) x += t;
    }
    if (lane == 31) wsum[wid] = x;
    __syncthreads();
    if (wid == 0) {
        int s = wsum[lane];
        #pragma unroll
        for (int d = 1; d < 32; d <<= 1) {
            int t = __shfl_up_sync(0xFFFFFFFFu, s, d);
            if (lane >= d) s += t;
        }
        wsum[lane] = s;
    }
    __syncthreads();
    if (i < n) {
        int excl = boff_s + (wid > 0 ? wsum[wid - 1] : 0) + x - v;
        g_rowstart[i] = excl;
        g_cursor[i]   = excl;
        g_dinvs[i] = rsqrtf((float)v + 1.0f);
        if (i == n - 1) g_rowstart[n] = excl + v;
    }
}

// ---------------- 3: fill CSR (src only, int4 over 4 edges) ----------------
__global__ void fill_kernel(const int* __restrict__ ei, int e) {
    int i = blockIdx.x * blockDim.x + threadIdx.x;
    int n4 = e >> 2;
    if (i < n4) {
        int4 s4 = ((const int4*)ei)[i];
        int4 d4 = ((const int4*)(ei + e))[i];
        g_src[atomicAdd(&g_cursor[d4.x], 1)] = s4.x;
        g_src[atomicAdd(&g_cursor[d4.y], 1)] = s4.y;
        g_src[atomicAdd(&g_cursor[d4.z], 1)] = s4.z;
        g_src[atomicAdd(&g_cursor[d4.w], 1)] = s4.w;
    }
    if (i == 0) {
        for (int j = n4 << 2; j < e; j++)
            g_src[atomicAdd(&g_cursor[ei[e + j]], 1)] = ei[j];
    }
}

// ---------------- 4: GEMM1  g_xw = fp16( (x @ W1) * dinvs )  --------------
__global__ void gemm1_kernel(const float* __restrict__ x,
                             const float* __restrict__ W1, int n) {
    __shared__ __align__(16) float Ws[128 * 32];
    __shared__ __align__(16) float xs[128 * 33];
    int tid = threadIdx.x;
    for (int i = tid; i < 128 * 32; i += 256) Ws[i] = W1[i];

    int tx = tid & 7;
    int ty = tid >> 3;
    int wid = tid >> 5, lane = tid & 31;
    int nodeBase = blockIdx.x * 128;

    unsigned long long acc2[4][2];
    #pragma unroll
    for (int i = 0; i < 4; i++) { acc2[i][0] = 0ull; acc2[i][1] = 0ull; }

    for (int kc = 0; kc < 4; kc++) {
        __syncthreads();
        for (int r = wid; r < 128; r += 8) {
            int gn = nodeBase + r;
            float v = 0.f;
            if (gn < n) v = x[gn * IN_CH + kc * 32 + lane];
            xs[r * 33 + lane] = v;
        }
        __syncthreads();
        #pragma unroll
        for (int k = 0; k < 32; k++) {
            const unsigned long long* wp =
                (const unsigned long long*)&Ws[(kc * 32 + k) * 32 + tx * 4];
            unsigned long long w0 = wp[0], w1 = wp[1];
            #pragma unroll
            for (int i = 0; i < 4; i++) {
                float xv = xs[(ty * 4 + i) * 33 + k];
                unsigned long long xp;
                asm("mov.b64 %0, {%1, %1};" : "=l"(xp) : "f"(xv));
                asm("fma.rn.f32x2 %0, %1, %2, %0;" : "+l"(acc2[i][0]) : "l"(xp), "l"(w0));
                asm("fma.rn.f32x2 %0, %1, %2, %0;" : "+l"(acc2[i][1]) : "l"(xp), "l"(w1));
            }
        }
    }
    #pragma unroll
    for (int i = 0; i < 4; i++) {
        int gn = nodeBase + ty * 4 + i;
        if (gn < n) {
            float ds = g_dinvs[gn];
            float r0, r1, r2, r3;
            asm("mov.b64 {%0, %1}, %2;" : "=f"(r0), "=f"(r1) : "l"(acc2[i][0]));
            asm("mov.b64 {%0, %1}, %2;" : "=f"(r2), "=f"(r3) : "l"(acc2[i][1]));
            __half2 h01 = __floats2half2_rn(r0 * ds, r1 * ds);
            __half2 h23 = __floats2half2_rn(r2 * ds, r3 * ds);
            uint2 st;
            st.x = *(unsigned*)&h01;
            st.y = *(unsigned*)&h23;
            *(uint2*)&g_xw[gn * HID + tx * 4] = st;
        }
    }
}

// ---------------- 5/6: fp16 gather-agg + bias + LN + ReLU + next GEMM -----
// MODE 0: in = g_xw,  out = g_hw2 (fp16) via W2[32,32]
// MODE 1: in = g_hw2, out = g_hw3 (fp32) via W3[32,2]
template <int MODE>
__global__ void agg_kernel(const float* __restrict__ b,
                           const float* __restrict__ g,
                           const float* __restrict__ be,
                           const float* __restrict__ Wn, int n) {
    const __half* __restrict__ xw = (MODE == 0) ? g_xw : g_hw2;
    __shared__ float Wns[32 * 32];
    __shared__ float tr[8 * 32];
    int tid = threadIdx.x, lane = tid & 31, wid = tid >> 5;
    int nload = (MODE == 0) ? 1024 : 64;
    for (int i = tid; i < nload; i += blockDim.x) Wns[i] = Wn[i];
    __syncthreads();

    int node = blockIdx.x * 8 + wid;
    if (node >= n) return;

    int rs = g_rowstart[node];
    int re = g_rowstart[node + 1];
    int cg = lane & 7;    // channel group: channels cg*4..cg*4+3
    int eg = lane >> 3;   // edge subgroup 0..3

    float f0 = 0.f, f1 = 0.f, f2 = 0.f, f3 = 0.f;
    for (int base = rs; base < re; base += 32) {
        int idx = base + lane;
        int sidx = (idx < re) ? g_src[idx] : ZROW;
        #pragma unroll
        for (int it = 0; it < 8; it++) {
            int s = __shfl_sync(0xFFFFFFFFu, sidx, it * 4 + eg);
            uint2 v = *(const uint2*)&xw[s * HID + cg * 4];   // 4 halves
            float2 lo = __half22float2(*(__half2*)&v.x);
            float2 hi = __half22float2(*(__half2*)&v.y);
            f0 += lo.x; f1 += lo.y; f2 += hi.x; f3 += hi.y;
        }
    }

    // reduce across edge subgroups (lane bits 3,4)
    #pragma unroll
    for (int m = 8; m <= 16; m <<= 1) {
        f0 += __shfl_xor_sync(0xFFFFFFFFu, f0, m);
        f1 += __shfl_xor_sync(0xFFFFFFFFu, f1, m);
        f2 += __shfl_xor_sync(0xFFFFFFFFu, f2, m);
        f3 += __shfl_xor_sync(0xFFFFFFFFu, f3, m);
    }
    if (eg == 0) {
        float4 st; st.x = f0; st.y = f1; st.z = f2; st.w = f3;
        *(float4*)&tr[wid * 32 + cg * 4] = st;
    }
    __syncwarp();
    float acc = tr[wid * 32 + lane];

    // self loop, scale by dinvs[dst], bias
    float ds = g_dinvs[node];
    acc = (acc + __half2float(xw[node * HID + lane])) * ds + b[lane];

    // LayerNorm over the 32 lanes
    float s = acc;
    #pragma unroll
    for (int d = 16; d; d >>= 1) s += __shfl_xor_sync(0xFFFFFFFFu, s, d);
    float mu = s * (1.0f / 32.0f);
    float diff = acc - mu;
    float v2 = diff * diff;
    #pragma unroll
    for (int d = 16; d; d >>= 1) v2 += __shfl_xor_sync(0xFFFFFFFFu, v2, d);
    float var = v2 * (1.0f / 32.0f);
    float y = diff * rsqrtf(var + LN_EPS) * g[lane] + be[lane];
    float h = fmaxf(y, 0.f);

    if (MODE == 0) {
        float o0 = 0.f, o1 = 0.f;
        #pragma unroll
        for (int k = 0; k < 32; k += 2) {
            float h0 = __shfl_sync(0xFFFFFFFFu, h, k);
            float h1 = __shfl_sync(0xFFFFFFFFu, h, k + 1);
            o0 = fmaf(h0, Wns[k * 32 + lane], o0);
            o1 = fmaf(h1, Wns[(k + 1) * 32 + lane], o1);
        }
        g_hw2[node * HID + lane] = __float2half((o0 + o1) * ds);
    } else {
        float p0 = h * Wns[lane * 2 + 0];
        float p1 = h * Wns[lane * 2 + 1];
        #pragma unroll
        for (int d = 16; d; d >>= 1) {
            p0 += __shfl_xor_sync(0xFFFFFFFFu, p0, d);
            p1 += __shfl_xor_sync(0xFFFFFFFFu, p1, d);
        }
        if (lane == 0) {
            float2 r; r.x = p0 * ds; r.y = p1 * ds;
            *(float2*)&g_hw3[node * 2] = r;
        }
    }
}

// ---------------- 7: final conv (OUT=2) ----------------
__global__ void final_kernel(const float* __restrict__ b3,
                             float* __restrict__ out, int n) {
    int tid = threadIdx.x, lane = tid & 31, wid = tid >> 5;
    int node = blockIdx.x * 8 + wid;
    if (node >= n) return;
    int rs = g_rowstart[node];
    int re = g_rowstart[node + 1];
    float a0 = 0.f, a1 = 0.f;
    for (int idx = rs + lane; idx < re; idx += 32) {
        float2 v = *(const float2*)&g_hw3[g_src[idx] * 2];
        a0 += v.x;
        a1 += v.y;
    }
    #pragma unroll
    for (int d = 16; d; d >>= 1) {
        a0 += __shfl_xor_sync(0xFFFFFFFFu, a0, d);
        a1 += __shfl_xor_sync(0xFFFFFFFFu, a1, d);
    }
    if (lane == 0) {
        float2 self = *(const float2*)&g_hw3[node * 2];
        float ds = g_dinvs[node];
        out[node * 2 + 0] = (a0 + self.x) * ds + b3[0];
        out[node * 2 + 1] = (a1 + self.y) * ds + b3[1];
    }
}

// ---------------- launch ----------------
extern "C" void kernel_launch(void* const* d_in, const int* in_sizes, int n_in,
                              void* d_out, int out_size) {
    const float* x   = (const float*)d_in[0];
    const int*   ei  = (const int*)d_in[1];
    const float* W1  = (const float*)d_in[2];
    const float* b1  = (const float*)d_in[3];
    const float* g1  = (const float*)d_in[4];
    const float* be1 = (const float*)d_in[5];
    const float* W2  = (const float*)d_in[6];
    const float* b2  = (const float*)d_in[7];
    const float* g2  = (const float*)d_in[8];
    const float* be2 = (const float*)d_in[9];
    const float* W3  = (const float*)d_in[10];
    const float* b3  = (const float*)d_in[11];
    float* out = (float*)d_out;

    int n = in_sizes[0] / IN_CH;   // 100000
    int e = in_sizes[1] / 2;       // 3200000
    int nb = (n + SCAN_B - 1) / SCAN_B;

    init_kernel<<<(n + 255) / 256, 256>>>(n);
    count_kernel<<<(e / 4 + 255) / 256, 256>>>(ei, e);
    blocksum_kernel<<<nb, SCAN_B>>>(n);
    scan2_kernel<<<nb, SCAN_B>>>(n, nb);
    fill_kernel<<<(e / 4 + 255) / 256, 256>>>(ei, e);
    gemm1_kernel<<<(n + 127) / 128, 256>>>(x, W1, n);
    agg_kernel<0><<<(n + 7) / 8, 256>>>(b1, g1, be1, W2, n);
    agg_kernel<1><<<(n + 7) / 8, 256>>>(b2, g2, be2, W3, n);
    final_kernel<<<(n + 7) / 8, 256>>>(b3, out, n);
}

// round 7
// speedup vs baseline: 1.2240x; 1.0835x over previous
#include <cuda_runtime.h>
#include <cuda_fp16.h>
#include <cuda_bf16.h>
#include <cstdint>

// GCN with folded normalization, fp16 feature tables, fp32 accumulation.
//   xw'[v] = (x@W)[v] * dinvs[v]    (stored fp16)
//   out[d] = dinvs[d] * ( sum_edges xw'[s] + xw'[d] ) + b
// CSR build: count_rank (atomic, records per-edge rank) -> scan -> place
// (atomic-free: pos = rowstart[dst] + rank). scan2 re-zeros g_cnt so no init
// kernel is needed (device globals are zero at load; ZROW rows never written).
// place and gemm1 are fused into one fat kernel (independent work, overlapped).

#define N_MAX 100000
#define E_MAX 3200000
#define IN_CH 128
#define HID   32
#define LN_EPS 1e-5f
#define SCAN_B 1024
#define ZROW  N_MAX

// ---------------- device scratch (zero-initialized at load) ----------------
__device__ int    g_cnt[N_MAX];            // stays zero between calls
__device__ int    g_rowstart[N_MAX + 1];
__device__ float  g_dinvs[N_MAX];
__device__ int    g_rank[E_MAX + 4];
__device__ int    g_src[E_MAX + 32];
__device__ int    g_bsum[128];
__device__ __align__(128) __half g_xw[(N_MAX + 1) * HID];   // ZROW row stays 0
__device__ __align__(128) __half g_hw2[(N_MAX + 1) * HID];  // ZROW row stays 0
__device__ float  g_hw3[(N_MAX + 1) * 2];                   // ZROW row stays 0

// ---------------- 1: degree counts + per-edge rank ----------------
__global__ void count_rank_kernel(const int* __restrict__ ei, int e) {
    int i = blockIdx.x * blockDim.x + threadIdx.x;
    int n4 = e >> 2;
    if (i < n4) {
        int4 d4 = ((const int4*)(ei + e))[i];
        int4 r4;
        r4.x = atomicAdd(&g_cnt[d4.x], 1);
        r4.y = atomicAdd(&g_cnt[d4.y], 1);
        r4.z = atomicAdd(&g_cnt[d4.z], 1);
        r4.w = atomicAdd(&g_cnt[d4.w], 1);
        ((int4*)g_rank)[i] = r4;
    }
    if (i == 0) {
        for (int j = n4 << 2; j < e; j++)
            g_rank[j] = atomicAdd(&g_cnt[ei[e + j]], 1);
    }
}

// ---------------- 2a: per-block sums of counts ----------------
__global__ void blocksum_kernel(int n) {
    __shared__ int ws[32];
    int tid = threadIdx.x, lane = tid & 31, wid = tid >> 5;
    int i = blockIdx.x * SCAN_B + tid;
    int v = (i < n) ? g_cnt[i] : 0;
    int s = v;
    #pragma unroll
    for (int d = 16; d; d >>= 1) s += __shfl_xor_sync(0xFFFFFFFFu, s, d);
    if (lane == 0) ws[wid] = s;
    __syncthreads();
    if (wid == 0) {
        int t = ws[lane];
        #pragma unroll
        for (int d = 16; d; d >>= 1) t += __shfl_xor_sync(0xFFFFFFFFu, t, d);
        if (lane == 0) g_bsum[blockIdx.x] = t;
    }
}

// ---------------- 2b: local scan + degree terms + re-zero counts ----------
__global__ void scan2_kernel(int n, int nb) {
    __shared__ int wsum[32];
    __shared__ int boff_s;
    int tid = threadIdx.x, lane = tid & 31, wid = tid >> 5;

    if (tid == 0) boff_s = 0;
    __syncthreads();
    if (tid < 128) {
        int bv = (tid < blockIdx.x) ? g_bsum[tid] : 0;
        #pragma unroll
        for (int d = 16; d; d >>= 1) bv += __shfl_xor_sync(0xFFFFFFFFu, bv, d);
        if (lane == 0 && bv) atomicAdd(&boff_s, bv);
    }

    int i = blockIdx.x * SCAN_B + tid;
    int v = (i < n) ? g_cnt[i] : 0;
    int x = v;
    #pragma unroll
    for (int d = 1; d < 32; d <<= 1) {
        int t = __shfl_up_sync(0xFFFFFFFFu, x, d);
        if (lane >= d) x += t;
    }
    if (lane == 31) wsum[wid] = x;
    __syncthreads();
    if (wid == 0) {
        int s = wsum[lane];
        #pragma unroll
        for (int d = 1; d < 32; d <<= 1) {
            int t = __shfl_up_sync(0xFFFFFFFFu, s, d);
            if (lane >= d) s += t;
        }
        wsum[lane] = s;
    }
    __syncthreads();
    if (i < n) {
        int excl = boff_s + (wid > 0 ? wsum[wid - 1] : 0) + x - v;
        g_rowstart[i] = excl;
        g_dinvs[i] = rsqrtf((float)v + 1.0f);
        g_cnt[i] = 0;                       // self-clean for next call
        if (i == n - 1) g_rowstart[n] = excl + v;
    }
}

// ---------------- 3+4 fat kernel: gemm1 branch || place branch ------------
// blocks [0, gemmBlocks): g_xw = fp16((x @ W1) * dinvs), 128 nodes/block
// blocks [gemmBlocks, ..): place CSR src (no atomics)
__global__ void place_gemm_kernel(const int* __restrict__ ei,
                                  const float* __restrict__ x,
                                  const float* __restrict__ W1,
                                  int n, int e, int gemmBlocks) {
    __shared__ __align__(16) float Ws[128 * 32];
    __shared__ __align__(16) float xs[128 * 33];
    int tid = threadIdx.x;

    if (blockIdx.x < gemmBlocks) {
        for (int i = tid; i < 128 * 32; i += 256) Ws[i] = W1[i];
        int tx = tid & 7;
        int ty = tid >> 3;
        int wid = tid >> 5, lane = tid & 31;
        int nodeBase = blockIdx.x * 128;

        unsigned long long acc2[4][2];
        #pragma unroll
        for (int i = 0; i < 4; i++) { acc2[i][0] = 0ull; acc2[i][1] = 0ull; }

        for (int kc = 0; kc < 4; kc++) {
            __syncthreads();
            for (int r = wid; r < 128; r += 8) {
                int gn = nodeBase + r;
                float v = 0.f;
                if (gn < n) v = x[gn * IN_CH + kc * 32 + lane];
                xs[r * 33 + lane] = v;
            }
            __syncthreads();
            #pragma unroll
            for (int k = 0; k < 32; k++) {
                const unsigned long long* wp =
                    (const unsigned long long*)&Ws[(kc * 32 + k) * 32 + tx * 4];
                unsigned long long w0 = wp[0], w1 = wp[1];
                #pragma unroll
                for (int i = 0; i < 4; i++) {
                    float xv = xs[(ty * 4 + i) * 33 + k];
                    unsigned long long xp;
                    asm("mov.b64 %0, {%1, %1};" : "=l"(xp) : "f"(xv));
                    asm("fma.rn.f32x2 %0, %1, %2, %0;" : "+l"(acc2[i][0]) : "l"(xp), "l"(w0));
                    asm("fma.rn.f32x2 %0, %1, %2, %0;" : "+l"(acc2[i][1]) : "l"(xp), "l"(w1));
                }
            }
        }
        #pragma unroll
        for (int i = 0; i < 4; i++) {
            int gn = nodeBase + ty * 4 + i;
            if (gn < n) {
                float ds = g_dinvs[gn];
                float r0, r1, r2, r3;
                asm("mov.b64 {%0, %1}, %2;" : "=f"(r0), "=f"(r1) : "l"(acc2[i][0]));
                asm("mov.b64 {%0, %1}, %2;" : "=f"(r2), "=f"(r3) : "l"(acc2[i][1]));
                __half2 h01 = __floats2half2_rn(r0 * ds, r1 * ds);
                __half2 h23 = __floats2half2_rn(r2 * ds, r3 * ds);
                uint2 st;
                st.x = *(unsigned*)&h01;
                st.y = *(unsigned*)&h23;
                *(uint2*)&g_xw[gn * HID + tx * 4] = st;
            }
        }
    } else {
        int i = (blockIdx.x - gemmBlocks) * blockDim.x + tid;
        int n4 = e >> 2;
        if (i < n4) {
            int4 s4 = ((const int4*)ei)[i];
            int4 d4 = ((const int4*)(ei + e))[i];
            int4 r4 = ((const int4*)g_rank)[i];
            g_src[g_rowstart[d4.x] + r4.x] = s4.x;
            g_src[g_rowstart[d4.y] + r4.y] = s4.y;
            g_src[g_rowstart[d4.z] + r4.z] = s4.z;
            g_src[g_rowstart[d4.w] + r4.w] = s4.w;
        }
        if (i == 0) {
            for (int j = n4 << 2; j < e; j++)
                g_src[g_rowstart[ei[e + j]] + g_rank[j]] = ei[j];
        }
    }
}

// ---------------- 5/6: fp16 gather-agg + bias + LN + ReLU + next GEMM -----
template <int MODE>
__global__ void agg_kernel(const float* __restrict__ b,
                           const float* __restrict__ g,
                           const float* __restrict__ be,
                           const float* __restrict__ Wn, int n) {
    const __half* __restrict__ xw = (MODE == 0) ? g_xw : g_hw2;
    __shared__ float Wns[32 * 32];
    __shared__ float tr[8 * 32];
    int tid = threadIdx.x, lane = tid & 31, wid = tid >> 5;
    int nload = (MODE == 0) ? 1024 : 64;
    for (int i = tid; i < nload; i += blockDim.x) Wns[i] = Wn[i];
    __syncthreads();

    int node = blockIdx.x * 8 + wid;
    if (node >= n) return;

    int rs = g_rowstart[node];
    int re = g_rowstart[node + 1];
    int cg = lane & 7;
    int eg = lane >> 3;

    float f0 = 0.f, f1 = 0.f, f2 = 0.f, f3 = 0.f;
    for (int base = rs; base < re; base += 32) {
        int idx = base + lane;
        int sidx = (idx < re) ? g_src[idx] : ZROW;
        #pragma unroll
        for (int it = 0; it < 8; it++) {
            int s = __shfl_sync(0xFFFFFFFFu, sidx, it * 4 + eg);
            uint2 v = *(const uint2*)&xw[s * HID + cg * 4];
            float2 lo = __half22float2(*(__half2*)&v.x);
            float2 hi = __half22float2(*(__half2*)&v.y);
            f0 += lo.x; f1 += lo.y; f2 += hi.x; f3 += hi.y;
        }
    }

    #pragma unroll
    for (int m = 8; m <= 16; m <<= 1) {
        f0 += __shfl_xor_sync(0xFFFFFFFFu, f0, m);
        f1 += __shfl_xor_sync(0xFFFFFFFFu, f1, m);
        f2 += __shfl_xor_sync(0xFFFFFFFFu, f2, m);
        f3 += __shfl_xor_sync(0xFFFFFFFFu, f3, m);
    }
    if (eg == 0) {
        float4 st; st.x = f0; st.y = f1; st.z = f2; st.w = f3;
        *(float4*)&tr[wid * 32 + cg * 4] = st;
    }
    __syncwarp();
    float acc = tr[wid * 32 + lane];

    float ds = g_dinvs[node];
    acc = (acc + __half2float(xw[node * HID + lane])) * ds + b[lane];

    float s = acc;
    #pragma unroll
    for (int d = 16; d; d >>= 1) s += __shfl_xor_sync(0xFFFFFFFFu, s, d);
    float mu = s * (1.0f / 32.0f);
    float diff = acc - mu;
    float v2 = diff * diff;
    #pragma unroll
    for (int d = 16; d; d >>= 1) v2 += __shfl_xor_sync(0xFFFFFFFFu, v2, d);
    float var = v2 * (1.0f / 32.0f);
    float y = diff * rsqrtf(var + LN_EPS) * g[lane] + be[lane];
    float h = fmaxf(y, 0.f);

    if (MODE == 0) {
        float o0 = 0.f, o1 = 0.f;
        #pragma unroll
        for (int k = 0; k < 32; k += 2) {
            float h0 = __shfl_sync(0xFFFFFFFFu, h, k);
            float h1 = __shfl_sync(0xFFFFFFFFu, h, k + 1);
            o0 = fmaf(h0, Wns[k * 32 + lane], o0);
            o1 = fmaf(h1, Wns[(k + 1) * 32 + lane], o1);
        }
        g_hw2[node * HID + lane] = __float2half((o0 + o1) * ds);
    } else {
        float p0 = h * Wns[lane * 2 + 0];
        float p1 = h * Wns[lane * 2 + 1];
        #pragma unroll
        for (int d = 16; d; d >>= 1) {
            p0 += __shfl_xor_sync(0xFFFFFFFFu, p0, d);
            p1 += __shfl_xor_sync(0xFFFFFFFFu, p1, d);
        }
        if (lane == 0) {
            float2 r; r.x = p0 * ds; r.y = p1 * ds;
            *(float2*)&g_hw3[node * 2] = r;
        }
    }
}

// ---------------- 7: final conv (OUT=2) ----------------
__global__ void final_kernel(const float* __restrict__ b3,
                             float* __restrict__ out, int n) {
    int tid = threadIdx.x, lane = tid & 31, wid = tid >> 5;
    int node = blockIdx.x * 8 + wid;
    if (node >= n) return;
    int rs = g_rowstart[node];
    int re = g_rowstart[node + 1];
    float a0 = 0.f, a1 = 0.f;
    for (int idx = rs + lane; idx < re; idx += 32) {
        float2 v = *(const float2*)&g_hw3[g_src[idx] * 2];
        a0 += v.x;
        a1 += v.y;
    }
    #pragma unroll
    for (int d = 16; d; d >>= 1) {
        a0 += __shfl_xor_sync(0xFFFFFFFFu, a0, d);
        a1 += __shfl_xor_sync(0xFFFFFFFFu, a1, d);
    }
    if (lane == 0) {
        float2 self = *(const float2*)&g_hw3[node * 2];
        float ds = g_dinvs[node];
        out[node * 2 + 0] = (a0 + self.x) * ds + b3[0];
        out[node * 2 + 1] = (a1 + self.y) * ds + b3[1];
    }
}

// ---------------- launch ----------------
extern "C" void kernel_launch(void* const* d_in, const int* in_sizes, int n_in,
                              void* d_out, int out_size) {
    const float* x   = (const float*)d_in[0];
    const int*   ei  = (const int*)d_in[1];
    const float* W1  = (const float*)d_in[2];
    const float* b1  = (const float*)d_in[3];
    const float* g1  = (const float*)d_in[4];
    const float* be1 = (const float*)d_in[5];
    const float* W2  = (const float*)d_in[6];
    const float* b2  = (const float*)d_in[7];
    const float* g2  = (const float*)d_in[8];
    const float* be2 = (const float*)d_in[9];
    const float* W3  = (const float*)d_in[10];
    const float* b3  = (const float*)d_in[11];
    float* out = (float*)d_out;

    int n = in_sizes[0] / IN_CH;   // 100000
    int e = in_sizes[1] / 2;       // 3200000
    int nb = (n + SCAN_B - 1) / SCAN_B;
    int gemmBlocks = (n + 127) / 128;
    int placeBlocks = ((e >> 2) + 255) / 256;

    count_rank_kernel<<<((e >> 2) + 255) / 256, 256>>>(ei, e);
    blocksum_kernel<<<nb, SCAN_B>>>(n);
    scan2_kernel<<<nb, SCAN_B>>>(n, nb);
    place_gemm_kernel<<<gemmBlocks + placeBlocks, 256>>>(ei, x, W1, n, e, gemmBlocks);
    agg_kernel<0><<<(n + 7) / 8, 256>>>(b1, g1, be1, W2, n);
    agg_kernel<1><<<(n + 7) / 8, 256>>>(b2, g2, be2, W3, n);
    final_kernel<<<(n + 7) / 8, 256>>>(b3, out, n);
}